// round 4
// baseline (speedup 1.0000x reference)
#include <cuda_runtime.h>
#include <math.h>

#define N_RES  8192
#define N_IN   128
#define BATCH  16
#define LEAK   0.9f

// Level-1: coarse bins of 32 rows
#define NB1    256
#define CAP1   27500          // Poisson(26214) + 8 sigma
#define DEPTH1 23             // smem stage depth (48KB static smem budget)
#define ITER1  4096           // entries per block-iteration (512 thr * 8)

// Level-2: fine shards = (row, col-quarter)
#define NQ     4
#define QCAP   320            // Poisson(205) + 8 sigma
#define NSH2   128            // fine shards per coarse bin (32 rows * 4 quarters)
#define DEPTH2 46
#define ITER2  4096

// ---------------------------------------------------------------------------
// Scratch (allocation-free __device__ globals)
__device__ __align__(16) float  g_z[N_RES * BATCH];
__device__ __align__(16) float  g_state_T[N_RES * BATCH];   // [row][batch]
__device__ __align__(16) float  g_x_T[N_IN * BATCH];
__device__ int    g_c1[NB1];
__device__ int    g_cursor[N_RES * NQ];
__device__ __align__(16) float2 g_bucket1[(size_t)NB1 * CAP1];        // 56 MB
__device__ __align__(16) float2 g_bucket[(size_t)N_RES * NQ * QCAP];  // 84 MB

__device__ __forceinline__ void red_add_v4(float* p, float a, float b, float c, float d) {
    asm volatile("red.global.add.v4.f32 [%0], {%1,%2,%3,%4};"
                 :: "l"(p), "f"(a), "f"(b), "f"(c), "f"(d) : "memory");
}
__device__ __forceinline__ float2 ldcg_f2(const float2* p) {
    float2 r;
    asm volatile("ld.global.cg.v2.f32 {%0,%1}, [%2];" : "=f"(r.x), "=f"(r.y) : "l"(p));
    return r;
}

// ---------------------------------------------------------------------------
// Kernel 1: init z with biases, zero cursors, transpose state and x.
__global__ void k_init(const float* __restrict__ state,
                       const float* __restrict__ x,
                       const float* __restrict__ res_bias,
                       const float* __restrict__ in_bias) {
    int i = blockIdx.x * blockDim.x + threadIdx.x;
    if (i < N_RES * BATCH) {
        int r = i >> 4;
        int b = i & (BATCH - 1);
        g_z[i]       = res_bias[r] + in_bias[r];
        g_state_T[i] = state[b * N_RES + r];
    }
    if (i < N_IN * BATCH) {
        int r = i >> 4;
        int b = i & (BATCH - 1);
        g_x_T[i] = x[b * N_IN + r];
    }
    if (i < N_RES * NQ) g_cursor[i] = 0;
    if (i < NB1)        g_c1[i] = 0;
}

// ---------------------------------------------------------------------------
// Kernel 2: coarse partition (row>>5) with smem write-combining.
__device__ __forceinline__ void place1(float v, int r, int c,
                                       int* scnt, float2* sbuf) {
    int b = r >> 5;
    int pos = atomicAdd(&scnt[b], 1);
    float2 e = make_float2(v, __int_as_float(c | ((r & 31) << 13)));
    if (pos < DEPTH1) {
        sbuf[b * DEPTH1 + pos] = e;
    } else {                                  // rare overflow: direct path
        int gp = atomicAdd(&g_c1[b], 1);
        if (gp < CAP1) g_bucket1[(size_t)b * CAP1 + gp] = e;
    }
}

__global__ void __launch_bounds__(512) k_part1(const float* __restrict__ vals,
                                               const int*   __restrict__ rows,
                                               const int*   __restrict__ cols,
                                               int nnz) {
    __shared__ int    scnt[NB1];
    __shared__ float2 sbuf[NB1 * DEPTH1];
    int tid  = threadIdx.x;
    int w    = tid >> 5;
    int lane = tid & 31;
    int nchunk = (nnz + ITER1 - 1) / ITER1;

    for (int chunk = blockIdx.x; chunk < nchunk; chunk += gridDim.x) {
        if (tid < NB1) scnt[tid] = 0;
        __syncthreads();

        int base = chunk * ITER1 + tid * 8;
        if (base + 8 <= nnz) {
            float4 v0 = *(const float4*)(vals + base);
            float4 v1 = *(const float4*)(vals + base + 4);
            int4   r0 = *(const int4*)(rows + base);
            int4   r1 = *(const int4*)(rows + base + 4);
            int4   c0 = *(const int4*)(cols + base);
            int4   c1 = *(const int4*)(cols + base + 4);
            place1(v0.x, r0.x, c0.x, scnt, sbuf);
            place1(v0.y, r0.y, c0.y, scnt, sbuf);
            place1(v0.z, r0.z, c0.z, scnt, sbuf);
            place1(v0.w, r0.w, c0.w, scnt, sbuf);
            place1(v1.x, r1.x, c1.x, scnt, sbuf);
            place1(v1.y, r1.y, c1.y, scnt, sbuf);
            place1(v1.z, r1.z, c1.z, scnt, sbuf);
            place1(v1.w, r1.w, c1.w, scnt, sbuf);
        } else {
            for (int k = 0; k < 8; k++) {
                int i = base + k;
                if (i < nnz) place1(vals[i], rows[i], cols[i], scnt, sbuf);
            }
        }
        __syncthreads();

        // Flush: each of 16 warps handles 16 bins; coalesced multi-entry writes.
        for (int b = w * 16; b < w * 16 + 16; b++) {
            int cnt = min(scnt[b], DEPTH1);
            if (cnt == 0) continue;
            int gbase = 0;
            if (lane == 0) gbase = atomicAdd(&g_c1[b], cnt);
            gbase = __shfl_sync(0xffffffffu, gbase, 0);
            for (int k = lane; k < cnt; k += 32) {
                int p = gbase + k;
                if (p < CAP1) g_bucket1[(size_t)b * CAP1 + p] = sbuf[b * DEPTH1 + k];
            }
        }
        __syncthreads();
    }
}

// ---------------------------------------------------------------------------
// Kernel 3: input SpMM (small: ~105K entries).
__global__ void k_in_spmm(const float* __restrict__ vals,
                          const int*   __restrict__ rows,
                          const int*   __restrict__ cols,
                          int nnz) {
    int i = blockIdx.x * blockDim.x + threadIdx.x;
    if (i >= nnz) return;
    float v = vals[i];
    int r = rows[i];
    int c = cols[i];
    const float4* s = reinterpret_cast<const float4*>(g_x_T + c * BATCH);
    float4 s0 = s[0], s1 = s[1], s2 = s[2], s3 = s[3];
    float* zp = g_z + r * BATCH;
    red_add_v4(zp + 0,  v * s0.x, v * s0.y, v * s0.z, v * s0.w);
    red_add_v4(zp + 4,  v * s1.x, v * s1.y, v * s1.z, v * s1.w);
    red_add_v4(zp + 8,  v * s2.x, v * s2.y, v * s2.z, v * s2.w);
    red_add_v4(zp + 12, v * s3.x, v * s3.y, v * s3.z, v * s3.w);
}

// ---------------------------------------------------------------------------
// Kernel 4: refine each coarse bin into (row, quarter) fine segments.
__device__ __forceinline__ void place2(float v, int packed, int bin,
                                       int* scnt, float2* sbuf) {
    int c  = packed & 8191;
    int r5 = (packed >> 13) & 31;
    int sh = (r5 << 2) | (c >> 11);             // 0..127 within bin
    int pos = atomicAdd(&scnt[sh], 1);
    float2 e = make_float2(v, __int_as_float(c));
    if (pos < DEPTH2) {
        sbuf[sh * DEPTH2 + pos] = e;
    } else {
        int shard = bin * NSH2 + sh;            // == row*NQ + quarter
        int gp = atomicAdd(&g_cursor[shard], 1);
        if (gp < QCAP) g_bucket[(size_t)shard * QCAP + gp] = e;
    }
}

__global__ void __launch_bounds__(512) k_part2() {
    __shared__ int    scnt[NSH2];
    __shared__ float2 sbuf[NSH2 * DEPTH2];
    int bin  = blockIdx.x >> 1;
    int half = blockIdx.x & 1;
    int tid  = threadIdx.x;
    int w    = tid >> 5;
    int lane = tid & 31;
    int n1 = min(g_c1[bin], CAP1);
    const float2* __restrict__ src = g_bucket1 + (size_t)bin * CAP1;

    for (int start = half * ITER2; start < n1; start += 2 * ITER2) {
        if (tid < NSH2) scnt[tid] = 0;
        __syncthreads();

        int base = start + tid * 8;
        if (base + 8 <= n1) {
            const float4* p4 = (const float4*)(src + base);
#pragma unroll
            for (int k = 0; k < 4; k++) {
                float4 q = p4[k];
                place2(q.x, __float_as_int(q.y), bin, scnt, sbuf);
                place2(q.z, __float_as_int(q.w), bin, scnt, sbuf);
            }
        } else {
            for (int k = 0; k < 8; k++) {
                int i = base + k;
                if (i < n1) {
                    float2 e = src[i];
                    place2(e.x, __float_as_int(e.y), bin, scnt, sbuf);
                }
            }
        }
        __syncthreads();

        // Flush: 16 warps x 8 shards each.
        for (int sh = w * 8; sh < w * 8 + 8; sh++) {
            int cnt = min(scnt[sh], DEPTH2);
            if (cnt == 0) continue;
            int shard = bin * NSH2 + sh;
            int gbase = 0;
            if (lane == 0) gbase = atomicAdd(&g_cursor[shard], cnt);
            gbase = __shfl_sync(0xffffffffu, gbase, 0);
            for (int k = lane; k < cnt; k += 32) {
                int p = gbase + k;
                if (p < QCAP) g_bucket[(size_t)shard * QCAP + p] = sbuf[sh * DEPTH2 + k];
            }
        }
        __syncthreads();
    }
}

// ---------------------------------------------------------------------------
// Kernel 5: gather. One warp per row; half-warp = one entry; lane&15 = batch.
__global__ void __launch_bounds__(256) k_gather(const float* __restrict__ state,
                                                float* __restrict__ out) {
    int warp_id = (blockIdx.x * blockDim.x + threadIdx.x) >> 5;
    if (warp_id >= N_RES) return;
    int r    = warp_id;
    int lane = threadIdx.x & 31;
    int half = lane >> 4;
    int b    = lane & 15;

    float acc0 = 0.0f, acc1 = 0.0f;
#pragma unroll
    for (int q = 0; q < NQ; q++) {
        int shard = r * NQ + q;
        int n = g_cursor[shard];
        if (n > QCAP) n = QCAP;
        const float2* __restrict__ seg = g_bucket + (size_t)shard * QCAP;

        int j = half;
        for (; j + 14 < n; j += 16) {
            float2 e0 = ldcg_f2(seg + j);
            float2 e1 = ldcg_f2(seg + j + 2);
            float2 e2 = ldcg_f2(seg + j + 4);
            float2 e3 = ldcg_f2(seg + j + 6);
            float2 e4 = ldcg_f2(seg + j + 8);
            float2 e5 = ldcg_f2(seg + j + 10);
            float2 e6 = ldcg_f2(seg + j + 12);
            float2 e7 = ldcg_f2(seg + j + 14);
            float s0 = __ldg(&g_state_T[__float_as_int(e0.y) * BATCH + b]);
            float s1 = __ldg(&g_state_T[__float_as_int(e1.y) * BATCH + b]);
            float s2 = __ldg(&g_state_T[__float_as_int(e2.y) * BATCH + b]);
            float s3 = __ldg(&g_state_T[__float_as_int(e3.y) * BATCH + b]);
            float s4 = __ldg(&g_state_T[__float_as_int(e4.y) * BATCH + b]);
            float s5 = __ldg(&g_state_T[__float_as_int(e5.y) * BATCH + b]);
            float s6 = __ldg(&g_state_T[__float_as_int(e6.y) * BATCH + b]);
            float s7 = __ldg(&g_state_T[__float_as_int(e7.y) * BATCH + b]);
            acc0 = fmaf(e0.x, s0, acc0);
            acc1 = fmaf(e1.x, s1, acc1);
            acc0 = fmaf(e2.x, s2, acc0);
            acc1 = fmaf(e3.x, s3, acc1);
            acc0 = fmaf(e4.x, s4, acc0);
            acc1 = fmaf(e5.x, s5, acc1);
            acc0 = fmaf(e6.x, s6, acc0);
            acc1 = fmaf(e7.x, s7, acc1);
        }
        for (; j < n; j += 2) {
            float2 e0 = ldcg_f2(seg + j);
            acc0 = fmaf(e0.x, __ldg(&g_state_T[__float_as_int(e0.y) * BATCH + b]), acc0);
        }
    }
    float acc = acc0 + acc1;
    acc += __shfl_xor_sync(0xffffffffu, acc, 16);

    if (lane < BATCH) {
        float z = acc + g_z[r * BATCH + lane];
        float s = state[lane * N_RES + r];
        out[lane * N_RES + r] = (1.0f - LEAK) * s + LEAK * erff(z);
    }
}

// ---------------------------------------------------------------------------
extern "C" void kernel_launch(void* const* d_in, const int* in_sizes, int n_in,
                              void* d_out, int out_size) {
    const float* state    = (const float*)d_in[0];
    const float* x        = (const float*)d_in[1];
    const float* res_vals = (const float*)d_in[2];
    const int*   res_rows = (const int*)  d_in[3];
    const int*   res_cols = (const int*)  d_in[4];
    const float* res_bias = (const float*)d_in[5];
    const float* in_vals  = (const float*)d_in[6];
    const int*   in_rows  = (const int*)  d_in[7];
    const int*   in_cols  = (const int*)  d_in[8];
    const float* in_bias  = (const float*)d_in[9];
    float* out = (float*)d_out;

    int res_nnz = in_sizes[2];
    int in_nnz  = in_sizes[6];

    k_init<<<(N_RES * BATCH + 255) / 256, 256>>>(state, x, res_bias, in_bias);

    k_part1<<<592, 512>>>(res_vals, res_rows, res_cols, res_nnz);

    k_in_spmm<<<(in_nnz + 255) / 256, 256>>>(in_vals, in_rows, in_cols, in_nnz);

    k_part2<<<2 * NB1, 512>>>();

    k_gather<<<(N_RES * 32 + 255) / 256, 256>>>(state, out);
}

// round 5
// speedup vs baseline: 1.2456x; 1.2456x over previous
#include <cuda_runtime.h>
#include <math.h>

#define N_RES  8192
#define N_IN   128
#define BATCH  16
#define LEAK   0.9f
#define NQ     4               // column quarters
#define QROWS  2048            // rows per quarter
#define QCAP   320             // per-(row,quarter) capacity; Poisson(205) + 8 sigma
#define SLICE_BYTES (QROWS * BATCH * sizeof(float))   // 128 KB

// ---------------------------------------------------------------------------
// Scratch (allocation-free __device__ globals)
__device__ __align__(16) float  g_z[N_RES * BATCH];        // bias + input-spmm accumulator
__device__ __align__(16) float  g_state_T[N_RES * BATCH];  // [row][batch]
__device__ __align__(16) float  g_x_T[N_IN * BATCH];
__device__ int    g_cursor[N_RES * NQ];
__device__ __align__(16) float2 g_bucket[(size_t)N_RES * NQ * QCAP];  // 84 MB

__device__ __forceinline__ void red_add_v4(float* p, float a, float b, float c, float d) {
    asm volatile("red.global.add.v4.f32 [%0], {%1,%2,%3,%4};"
                 :: "l"(p), "f"(a), "f"(b), "f"(c), "f"(d) : "memory");
}
__device__ __forceinline__ float2 ldcg_f2(const float2* p) {
    float2 r;
    asm volatile("ld.global.cg.v2.f32 {%0,%1}, [%2];" : "=f"(r.x), "=f"(r.y) : "l"(p));
    return r;
}

// ---------------------------------------------------------------------------
// Kernel 1: init z with biases, zero shard cursors, transpose state and x.
__global__ void k_init(const float* __restrict__ state,
                       const float* __restrict__ x,
                       const float* __restrict__ res_bias,
                       const float* __restrict__ in_bias) {
    int i = blockIdx.x * blockDim.x + threadIdx.x;
    if (i < N_RES * BATCH) {
        int r = i >> 4;
        int b = i & (BATCH - 1);
        g_z[i]       = res_bias[r] + in_bias[r];
        g_state_T[i] = state[b * N_RES + r];
    }
    if (i < N_IN * BATCH) {
        int r = i >> 4;
        int b = i & (BATCH - 1);
        g_x_T[i] = x[b * N_IN + r];
    }
    if (i < N_RES * NQ) g_cursor[i] = 0;
}

// ---------------------------------------------------------------------------
// Kernel 2: input SpMM (small: ~105K entries).
__global__ void k_in_spmm(const float* __restrict__ vals,
                          const int*   __restrict__ rows,
                          const int*   __restrict__ cols,
                          int nnz) {
    int i = blockIdx.x * blockDim.x + threadIdx.x;
    if (i >= nnz) return;
    float v = vals[i];
    int r = rows[i];
    int c = cols[i];
    const float4* s = reinterpret_cast<const float4*>(g_x_T + c * BATCH);
    float4 s0 = s[0], s1 = s[1], s2 = s[2], s3 = s[3];
    float* zp = g_z + r * BATCH;
    red_add_v4(zp + 0,  v * s0.x, v * s0.y, v * s0.z, v * s0.w);
    red_add_v4(zp + 4,  v * s1.x, v * s1.y, v * s1.z, v * s1.w);
    red_add_v4(zp + 8,  v * s2.x, v * s2.y, v * s2.z, v * s2.w);
    red_add_v4(zp + 12, v * s3.x, v * s3.y, v * s3.z, v * s3.w);
}

// ---------------------------------------------------------------------------
// Kernel 3: direct scatter into (row, col-quarter) fine shards (R3 version,
// 4 independent atomic chains per thread).
__global__ void __launch_bounds__(256) k_scatter(const float* __restrict__ vals,
                                                 const int*   __restrict__ rows,
                                                 const int*   __restrict__ cols,
                                                 int nnz) {
    int i0 = (blockIdx.x * blockDim.x + threadIdx.x) * 4;
#pragma unroll
    for (int k = 0; k < 4; k++) {
        int i = i0 + k;
        if (i < nnz) {
            int   r = __ldg(rows + i);
            int   c = __ldg(cols + i);
            float v = __ldg(vals + i);
            int shard = r * NQ + (c >> 11);
            int pos = atomicAdd(&g_cursor[shard], 1);
            if (pos < QCAP) {
                g_bucket[(size_t)shard * QCAP + pos] =
                    make_float2(v, __int_as_float(c));
            }
        }
    }
}

// ---------------------------------------------------------------------------
// Kernel 4: gather with smem-resident state quarter-slice.
// Block = 1024 threads = 32 warps = 32 output rows. For each quarter:
// stage 2048 rows x 16 batch of state (128 KB) into smem, then each warp
// drains its row's quarter segment; half-warp = one entry, lane&15 = batch.
__global__ void __launch_bounds__(1024) k_gather(const float* __restrict__ state,
                                                 float* __restrict__ out) {
    extern __shared__ float s_state[];           // QROWS * BATCH floats (128 KB)
    int tid   = threadIdx.x;
    int w     = tid >> 5;                        // warp -> local row
    int lane  = tid & 31;
    int half  = lane >> 4;
    int b     = lane & 15;
    int r     = blockIdx.x * 32 + w;             // output row

    float acc0 = 0.0f, acc1 = 0.0f;

#pragma unroll 1
    for (int q = 0; q < NQ; q++) {
        // Stage quarter slice: 2048*16 floats = 8192 float4, 8 per thread.
        const float4* src = reinterpret_cast<const float4*>(g_state_T + q * QROWS * BATCH);
        float4* dst = reinterpret_cast<float4*>(s_state);
#pragma unroll
        for (int k = 0; k < 8; k++)
            dst[tid + k * 1024] = src[tid + k * 1024];
        __syncthreads();

        int shard = r * NQ + q;
        int n = g_cursor[shard];
        if (n > QCAP) n = QCAP;
        const float2* __restrict__ seg = g_bucket + (size_t)shard * QCAP;
        int cbase = q << 11;

        int j = half;
        for (; j + 14 < n; j += 16) {
            float2 e0 = ldcg_f2(seg + j);
            float2 e1 = ldcg_f2(seg + j + 2);
            float2 e2 = ldcg_f2(seg + j + 4);
            float2 e3 = ldcg_f2(seg + j + 6);
            float2 e4 = ldcg_f2(seg + j + 8);
            float2 e5 = ldcg_f2(seg + j + 10);
            float2 e6 = ldcg_f2(seg + j + 12);
            float2 e7 = ldcg_f2(seg + j + 14);
            float s0 = s_state[(__float_as_int(e0.y) - cbase) * BATCH + b];
            float s1 = s_state[(__float_as_int(e1.y) - cbase) * BATCH + b];
            float s2 = s_state[(__float_as_int(e2.y) - cbase) * BATCH + b];
            float s3 = s_state[(__float_as_int(e3.y) - cbase) * BATCH + b];
            float s4 = s_state[(__float_as_int(e4.y) - cbase) * BATCH + b];
            float s5 = s_state[(__float_as_int(e5.y) - cbase) * BATCH + b];
            float s6 = s_state[(__float_as_int(e6.y) - cbase) * BATCH + b];
            float s7 = s_state[(__float_as_int(e7.y) - cbase) * BATCH + b];
            acc0 = fmaf(e0.x, s0, acc0);
            acc1 = fmaf(e1.x, s1, acc1);
            acc0 = fmaf(e2.x, s2, acc0);
            acc1 = fmaf(e3.x, s3, acc1);
            acc0 = fmaf(e4.x, s4, acc0);
            acc1 = fmaf(e5.x, s5, acc1);
            acc0 = fmaf(e6.x, s6, acc0);
            acc1 = fmaf(e7.x, s7, acc1);
        }
        for (; j < n; j += 2) {
            float2 e0 = ldcg_f2(seg + j);
            acc0 = fmaf(e0.x, s_state[(__float_as_int(e0.y) - cbase) * BATCH + b], acc0);
        }
        __syncthreads();   // slice reuse barrier before next quarter overwrite
    }

    float acc = acc0 + acc1;
    acc += __shfl_xor_sync(0xffffffffu, acc, 16);

    if (lane < BATCH) {
        float z = acc + g_z[r * BATCH + lane];
        float s = state[lane * N_RES + r];
        out[lane * N_RES + r] = (1.0f - LEAK) * s + LEAK * erff(z);
    }
}

// ---------------------------------------------------------------------------
extern "C" void kernel_launch(void* const* d_in, const int* in_sizes, int n_in,
                              void* d_out, int out_size) {
    const float* state    = (const float*)d_in[0];
    const float* x        = (const float*)d_in[1];
    const float* res_vals = (const float*)d_in[2];
    const int*   res_rows = (const int*)  d_in[3];
    const int*   res_cols = (const int*)  d_in[4];
    const float* res_bias = (const float*)d_in[5];
    const float* in_vals  = (const float*)d_in[6];
    const int*   in_rows  = (const int*)  d_in[7];
    const int*   in_cols  = (const int*)  d_in[8];
    const float* in_bias  = (const float*)d_in[9];
    float* out = (float*)d_out;

    int res_nnz = in_sizes[2];
    int in_nnz  = in_sizes[6];

    static int smem_set = 0;
    if (!smem_set) {
        cudaFuncSetAttribute(k_gather, cudaFuncAttributeMaxDynamicSharedMemorySize,
                             (int)SLICE_BYTES);
        smem_set = 1;
    }

    // Launch order chosen so k_gather is the 4th launch (ncu slot).
    k_init<<<(N_RES * BATCH + 255) / 256, 256>>>(state, x, res_bias, in_bias);

    k_in_spmm<<<(in_nnz + 255) / 256, 256>>>(in_vals, in_rows, in_cols, in_nnz);

    int scatter_threads = (res_nnz + 3) / 4;
    k_scatter<<<(scatter_threads + 255) / 256, 256>>>(res_vals, res_rows, res_cols, res_nnz);

    k_gather<<<N_RES / 32, 1024, SLICE_BYTES>>>(state, out);
}

// round 6
// speedup vs baseline: 1.2957x; 1.0402x over previous
#include <cuda_runtime.h>
#include <math.h>

#define N_RES  8192
#define N_IN   128
#define BATCH  16
#define LEAK   0.9f
#define NBG    4                 // batch groups
#define BG     4                 // batches per group
#define NCHUNK 38
#define ACC_BLOCKS (NCHUNK * NBG)        // 152 = GB300 SM count
#define ACC_SMEM (N_RES * BG * sizeof(float))   // 128 KB

// ---------------------------------------------------------------------------
// Scratch (allocation-free __device__ globals)
__device__ __align__(16) float g_z[N_RES * BATCH];          // [row][16]
__device__ __align__(16) float g_slab[NBG * N_RES * BG];    // state as [bg][row][4]
__device__ __align__(16) float g_x_T[N_IN * BATCH];         // [col][16]

__device__ __forceinline__ void red_add_v4(float* p, float a, float b, float c, float d) {
    asm volatile("red.global.add.v4.f32 [%0], {%1,%2,%3,%4};"
                 :: "l"(p), "f"(a), "f"(b), "f"(c), "f"(d) : "memory");
}

// ---------------------------------------------------------------------------
// Kernel 1: z = biases, transpose x.
__global__ void k_init_misc(const float* __restrict__ x,
                            const float* __restrict__ res_bias,
                            const float* __restrict__ in_bias) {
    int i = blockIdx.x * blockDim.x + threadIdx.x;
    if (i < N_RES * BATCH) {
        int r = i >> 4;
        g_z[i] = res_bias[r] + in_bias[r];
    }
    if (i < N_IN * BATCH) {
        int r = i >> 4;
        int b = i & (BATCH - 1);
        g_x_T[i] = x[b * N_IN + r];
    }
}

// ---------------------------------------------------------------------------
// Kernel 2: build state slabs [bg][row][4] from state [b][row].
__global__ void k_init_slab(const float* __restrict__ state) {
    int i = blockIdx.x * blockDim.x + threadIdx.x;   // over 131072, coalesced read
    if (i < N_RES * BATCH) {
        int b = i >> 13;            // batch
        int r = i & (N_RES - 1);    // row
        g_slab[(b >> 2) * (N_RES * BG) + r * BG + (b & 3)] = state[i];
    }
}

// ---------------------------------------------------------------------------
// Kernel 3: input SpMM (small: ~105K entries) via global v4 reductions.
__global__ void k_in_spmm(const float* __restrict__ vals,
                          const int*   __restrict__ rows,
                          const int*   __restrict__ cols,
                          int nnz) {
    int i = blockIdx.x * blockDim.x + threadIdx.x;
    if (i >= nnz) return;
    float v = vals[i];
    int r = rows[i];
    int c = cols[i];
    const float4* s = reinterpret_cast<const float4*>(g_x_T + c * BATCH);
    float4 s0 = s[0], s1 = s[1], s2 = s[2], s3 = s[3];
    float* zp = g_z + r * BATCH;
    red_add_v4(zp + 0,  v * s0.x, v * s0.y, v * s0.z, v * s0.w);
    red_add_v4(zp + 4,  v * s1.x, v * s1.y, v * s1.z, v * s1.w);
    red_add_v4(zp + 8,  v * s2.x, v * s2.y, v * s2.z, v * s2.w);
    red_add_v4(zp + 12, v * s3.x, v * s3.y, v * s3.z, v * s3.w);
}

// ---------------------------------------------------------------------------
// Kernel 4 (ncu slot): reservoir SpMM accumulated in shared memory.
// Block = (chunk, batch-group). sz[8192][4] = 128 KB. Entry handled by a
// quad of lanes (j = batch-in-group). No global scatter, no sorting, exact.
__global__ void __launch_bounds__(1024) k_accum(const float* __restrict__ vals,
                                                const int*   __restrict__ rows,
                                                const int*   __restrict__ cols,
                                                int nnz) {
    extern __shared__ float sz[];            // N_RES * BG floats
    int tid   = threadIdx.x;
    int bg    = blockIdx.x & (NBG - 1);
    int chunk = blockIdx.x >> 2;

    float4* z4 = reinterpret_cast<float4*>(sz);
    for (int k = tid; k < N_RES; k += 1024)
        z4[k] = make_float4(0.f, 0.f, 0.f, 0.f);
    __syncthreads();

    int per   = (nnz + NCHUNK - 1) / NCHUNK;
    int start = chunk * per;
    int end   = min(nnz, start + per);

    const float* __restrict__ slab = g_slab + bg * (N_RES * BG);
    int quad = tid >> 2;          // 0..255: entry slot
    int j    = tid & 3;           // batch-in-group

    int i = start + quad;
    // 4 independent iterations in flight: 12 LDGs issue before first atomic.
    for (; i + 768 < end; i += 1024) {
        int   r0 = rows[i];        int   c0 = cols[i];        float v0 = vals[i];
        int   r1 = rows[i + 256];  int   c1 = cols[i + 256];  float v1 = vals[i + 256];
        int   r2 = rows[i + 512];  int   c2 = cols[i + 512];  float v2 = vals[i + 512];
        int   r3 = rows[i + 768];  int   c3 = cols[i + 768];  float v3 = vals[i + 768];
        float s0 = slab[c0 * BG + j];
        float s1 = slab[c1 * BG + j];
        float s2 = slab[c2 * BG + j];
        float s3 = slab[c3 * BG + j];
        atomicAdd(&sz[r0 * BG + j], v0 * s0);
        atomicAdd(&sz[r1 * BG + j], v1 * s1);
        atomicAdd(&sz[r2 * BG + j], v2 * s2);
        atomicAdd(&sz[r3 * BG + j], v3 * s3);
    }
    for (; i < end; i += 256) {
        int   r = rows[i];
        int   c = cols[i];
        float v = vals[i];
        atomicAdd(&sz[r * BG + j], v * slab[c * BG + j]);
    }
    __syncthreads();

    // Flush partials: one v4 reduction per row into g_z[row][bg*4 .. +4).
    for (int r = tid; r < N_RES; r += 1024) {
        float4 zv = z4[r];
        red_add_v4(g_z + r * BATCH + bg * BG, zv.x, zv.y, zv.z, zv.w);
    }
}

// ---------------------------------------------------------------------------
// Kernel 5: epilogue  out[b,r] = 0.1*state[b,r] + 0.9*erf(z[r,b])
__global__ void k_final(const float* __restrict__ state,
                        float* __restrict__ out) {
    int i = blockIdx.x * blockDim.x + threadIdx.x;
    if (i >= BATCH * N_RES) return;
    int b = i >> 13;
    int r = i & (N_RES - 1);
    float z = g_z[r * BATCH + b];
    out[i] = (1.0f - LEAK) * state[i] + LEAK * erff(z);
}

// ---------------------------------------------------------------------------
extern "C" void kernel_launch(void* const* d_in, const int* in_sizes, int n_in,
                              void* d_out, int out_size) {
    const float* state    = (const float*)d_in[0];
    const float* x        = (const float*)d_in[1];
    const float* res_vals = (const float*)d_in[2];
    const int*   res_rows = (const int*)  d_in[3];
    const int*   res_cols = (const int*)  d_in[4];
    const float* res_bias = (const float*)d_in[5];
    const float* in_vals  = (const float*)d_in[6];
    const int*   in_rows  = (const int*)  d_in[7];
    const int*   in_cols  = (const int*)  d_in[8];
    const float* in_bias  = (const float*)d_in[9];
    float* out = (float*)d_out;

    int res_nnz = in_sizes[2];
    int in_nnz  = in_sizes[6];

    static int smem_set = 0;
    if (!smem_set) {
        cudaFuncSetAttribute(k_accum, cudaFuncAttributeMaxDynamicSharedMemorySize,
                             (int)ACC_SMEM);
        smem_set = 1;
    }

    // Order chosen so k_accum is the 4th launch (ncu capture slot).
    k_init_misc<<<(N_RES * BATCH + 255) / 256, 256>>>(x, res_bias, in_bias);

    k_init_slab<<<(N_RES * BATCH + 255) / 256, 256>>>(state);

    k_in_spmm<<<(in_nnz + 255) / 256, 256>>>(in_vals, in_rows, in_cols, in_nnz);

    k_accum<<<ACC_BLOCKS, 1024, ACC_SMEM>>>(res_vals, res_rows, res_cols, res_nnz);

    k_final<<<(BATCH * N_RES + 255) / 256, 256>>>(state, out);
}